// round 11
// baseline (speedup 1.0000x reference)
#include <cuda_runtime.h>
#include <cstdint>

// out[i] = W[inputs[i] - 1];  N = 16384*200 = 3,276,800;  W: 200 floats.
// Index dtype probe: idx_raw[1]==0 -> int64 (high word of elem 0), else int32.
//
// Exact one-wave launch: 592 CTAs x 512 thr = 303,104 threads = chip
// residency cap (4 CTAs/SM, 148 SMs). Work = 12,800 warp-units
// (1 unit = 8 elems/lane). Pass 0: warp-unit wid*592+bid (all warps).
// Pass 1: +9472 (only warps with wu0 < 3328 = warps 0..5 of EVERY CTA,
// so heavy/light warps distribute identically on every SM -> no tail).
// v8.b32 ops, L2 evict_last (idx) / evict_first (out), replicated smem.

#define N_TOTAL   (16384 * 200)
#define MAX_RANKS 200
#define TPB       512
#define NBLK      592
#define NWARPS    ((NBLK * TPB) / 32)   // 9472
#define WU_TOTAL  (N_TOTAL / (32 * 8))  // 12800

struct V8 { uint32_t r0,r1,r2,r3,r4,r5,r6,r7; };

__device__ __forceinline__ V8 ldg_pin8(const void* p) {
    V8 v;
    asm volatile("ld.global.nc.L2::evict_last.v8.b32 "
                 "{%0,%1,%2,%3,%4,%5,%6,%7}, [%8];"
                 : "=r"(v.r0), "=r"(v.r1), "=r"(v.r2), "=r"(v.r3),
                   "=r"(v.r4), "=r"(v.r5), "=r"(v.r6), "=r"(v.r7)
                 : "l"(p));
    return v;
}

__device__ __forceinline__ void stg_stream8(void* p, const float* f) {
    asm volatile("st.global.L2::evict_first.v8.b32 "
                 "[%0], {%1,%2,%3,%4,%5,%6,%7,%8};"
                 :: "l"(p),
                    "f"(f[0]), "f"(f[1]), "f"(f[2]), "f"(f[3]),
                    "f"(f[4]), "f"(f[5]), "f"(f[6]), "f"(f[7])
                 : "memory");
}

__device__ __forceinline__ void do_unit(long long unit, bool is64,
                                        const char* __restrict__ ib,
                                        char* __restrict__ ob,
                                        const float* __restrict__ sWl)
{
    float r[8];
    if (is64) {
        V8 a = ldg_pin8(ib + unit * 64);        // low words at even regs
        V8 b = ldg_pin8(ib + unit * 64 + 32);
        r[0] = sWl[((int)a.r0 - 1) * 32];
        r[1] = sWl[((int)a.r2 - 1) * 32];
        r[2] = sWl[((int)a.r4 - 1) * 32];
        r[3] = sWl[((int)a.r6 - 1) * 32];
        r[4] = sWl[((int)b.r0 - 1) * 32];
        r[5] = sWl[((int)b.r2 - 1) * 32];
        r[6] = sWl[((int)b.r4 - 1) * 32];
        r[7] = sWl[((int)b.r6 - 1) * 32];
    } else {
        V8 a = ldg_pin8(ib + unit * 32);
        r[0] = sWl[((int)a.r0 - 1) * 32];
        r[1] = sWl[((int)a.r1 - 1) * 32];
        r[2] = sWl[((int)a.r2 - 1) * 32];
        r[3] = sWl[((int)a.r3 - 1) * 32];
        r[4] = sWl[((int)a.r4 - 1) * 32];
        r[5] = sWl[((int)a.r5 - 1) * 32];
        r[6] = sWl[((int)a.r6 - 1) * 32];
        r[7] = sWl[((int)a.r7 - 1) * 32];
    }
    stg_stream8(ob + unit * 32, r);
}

__global__ __launch_bounds__(TPB)
void bias_gather_kernel(const uint32_t* __restrict__ idx_raw,
                        const float* __restrict__ W,
                        float* __restrict__ out)
{
    // 32-way replicated W: sW[rank*32 + lane] -> bank == lane, conflict-free.
    __shared__ float sW[MAX_RANKS * 32];

    const int tid  = threadIdx.x;
    const int lane = tid & 31;
    const int wid  = tid >> 5;

    // Warp-unit ids: SM-uniform heavy/light split.
    const int wu0 = wid * NBLK + (int)blockIdx.x;          // 0 .. 9471
    const int wu1 = wu0 + NWARPS;                          // second pass
    const long long unit0 = (long long)wu0 * 32 + lane;

    // ---- Front-batch pass-0 index loads (overlap with W fill) ----
    const uint32_t probe = idx_raw[1];      // 0 => int64 indices
    const bool is64 = (probe == 0u);
    const char* ib = reinterpret_cast<const char*>(idx_raw);
    char*       ob = reinterpret_cast<char*>(out);

    V8 a, b;
    if (is64) {
        a = ldg_pin8(ib + unit0 * 64);
        b = ldg_pin8(ib + unit0 * 64 + 32);
    } else {
        a = ldg_pin8(ib + unit0 * 32);
    }

    // ---- Fill replicated W while loads fly ----
    #pragma unroll
    for (int k = wid; k < MAX_RANKS; k += TPB / 32) {
        float v = W[k];                  // warp-uniform addr: 1 sector
        sW[k * 32 + lane] = v;           // conflict-free STS
    }
    __syncthreads();

    const float* sWl = sW + lane;

    // ---- Pass 0: gather + streaming store ----
    {
        float r[8];
        if (is64) {
            r[0] = sWl[((int)a.r0 - 1) * 32];
            r[1] = sWl[((int)a.r2 - 1) * 32];
            r[2] = sWl[((int)a.r4 - 1) * 32];
            r[3] = sWl[((int)a.r6 - 1) * 32];
            r[4] = sWl[((int)b.r0 - 1) * 32];
            r[5] = sWl[((int)b.r2 - 1) * 32];
            r[6] = sWl[((int)b.r4 - 1) * 32];
            r[7] = sWl[((int)b.r6 - 1) * 32];
        } else {
            r[0] = sWl[((int)a.r0 - 1) * 32];
            r[1] = sWl[((int)a.r1 - 1) * 32];
            r[2] = sWl[((int)a.r2 - 1) * 32];
            r[3] = sWl[((int)a.r3 - 1) * 32];
            r[4] = sWl[((int)a.r4 - 1) * 32];
            r[5] = sWl[((int)a.r5 - 1) * 32];
            r[6] = sWl[((int)a.r6 - 1) * 32];
            r[7] = sWl[((int)a.r7 - 1) * 32];
        }
        stg_stream8(ob + unit0 * 32, r);
    }

    // ---- Pass 1: warps 0..5 of every CTA take the remaining units ----
    if (wu1 < WU_TOTAL) {
        const long long unit1 = (long long)wu1 * 32 + lane;
        do_unit(unit1, is64, ib, ob, sWl);
    }
}

extern "C" void kernel_launch(void* const* d_in, const int* in_sizes, int n_in,
                              void* d_out, int out_size)
{
    const uint32_t* idx = (const uint32_t*)d_in[0];  // inputs [16384, 200]
    const float*    W   = (const float*)d_in[1];     // [200, 1]
    float*          out = (float*)d_out;

    bias_gather_kernel<<<NBLK, TPB>>>(idx, W, out);
}